// round 12
// baseline (speedup 1.0000x reference)
#include <cuda_runtime.h>
#include <cuda_bf16.h>
#include <cstdint>

// B=2, S=512, D=256, N=16, DC=4, DI=512, CHUNK=32, rows=1024

// ---------------- scratch ----------------
__device__ __nv_bfloat16 g_xpb [1024*512];
__device__ float         g_sz  [1024*512];
__device__ float         g_xact[1024*512];
__device__ float         g_decay[1024*512];
__device__ __nv_bfloat16 g_Bmb [1024*16];
__device__ __nv_bfloat16 g_Cmb [1024*16];
__device__ float         g_invdeg[1024];
__device__ float         g_any [1024];
__device__ __nv_bfloat16 g_Pb  [1024*512];
__device__ __nv_bfloat16 g_Woutb[256*512];
__device__ __nv_bfloat16 g_adjb [2*512*512];
__device__ __nv_bfloat16 g_cwb  [4*512*512];   // [kc][n][k]

// ---------------- mma helpers ----------------
__device__ __forceinline__ uint32_t smem_u32(const void* p) {
    return (uint32_t)__cvta_generic_to_shared(p);
}
__device__ __forceinline__ void ldsm_x4(uint32_t* r, uint32_t a) {
    asm volatile("ldmatrix.sync.aligned.m8n8.x4.shared.b16 {%0,%1,%2,%3}, [%4];\n"
                 : "=r"(r[0]), "=r"(r[1]), "=r"(r[2]), "=r"(r[3]) : "r"(a));
}
__device__ __forceinline__ void ldsm_x4t(uint32_t* r, uint32_t a) {
    asm volatile("ldmatrix.sync.aligned.m8n8.x4.trans.shared.b16 {%0,%1,%2,%3}, [%4];\n"
                 : "=r"(r[0]), "=r"(r[1]), "=r"(r[2]), "=r"(r[3]) : "r"(a));
}
__device__ __forceinline__ void mma_bf16(float* c, const uint32_t* a, const uint32_t* b) {
    asm volatile(
        "mma.sync.aligned.m16n8k16.row.col.f32.bf16.bf16.f32 "
        "{%0,%1,%2,%3}, {%4,%5,%6,%7}, {%8,%9}, {%0,%1,%2,%3};\n"
        : "+f"(c[0]), "+f"(c[1]), "+f"(c[2]), "+f"(c[3])
        : "r"(a[0]), "r"(a[1]), "r"(a[2]), "r"(a[3]), "r"(b[0]), "r"(b[1]));
}
__device__ __forceinline__ uint4 pack8(float4 a, float4 b) {
    __nv_bfloat162 r0 = __floats2bfloat162_rn(a.x, a.y);
    __nv_bfloat162 r1 = __floats2bfloat162_rn(a.z, a.w);
    __nv_bfloat162 r2 = __floats2bfloat162_rn(b.x, b.y);
    __nv_bfloat162 r3 = __floats2bfloat162_rn(b.z, b.w);
    uint4 u;
    u.x = *(uint32_t*)&r0; u.y = *(uint32_t*)&r1;
    u.z = *(uint32_t*)&r2; u.w = *(uint32_t*)&r3;
    return u;
}
__device__ __forceinline__ float dot16_bf16(const __nv_bfloat16* h, const __nv_bfloat16* c) {
    uint4 h0 = *(const uint4*)h,       h1 = *(const uint4*)(h + 8);
    uint4 c0 = *(const uint4*)c,       c1 = *(const uint4*)(c + 8);
    const __nv_bfloat162* hp0 = (const __nv_bfloat162*)&h0;
    const __nv_bfloat162* hp1 = (const __nv_bfloat162*)&h1;
    const __nv_bfloat162* cp0 = (const __nv_bfloat162*)&c0;
    const __nv_bfloat162* cp1 = (const __nv_bfloat162*)&c1;
    float y = 0.f;
#pragma unroll
    for (int q = 0; q < 4; ++q) {
        float2 a = __bfloat1622float2(hp0[q]), bb = __bfloat1622float2(cp0[q]);
        y = fmaf(a.x, bb.x, y); y = fmaf(a.y, bb.y, y);
        float2 a1 = __bfloat1622float2(hp1[q]), b1 = __bfloat1622float2(cp1[q]);
        y = fmaf(a1.x, b1.x, y); y = fmaf(a1.y, b1.y, y);
    }
    return y;
}
// 0.1 * silu(x) via hardware tanh:  x*(0.05 + 0.05*tanh(0.5x))
__device__ __forceinline__ float boost_silu(float x) {
    float th;
    asm("tanh.approx.f32 %0, %1;" : "=f"(th) : "f"(x * 0.5f));
    return x * fmaf(th, 0.05f, 0.05f);
}

// ---------------- GEMM ids ----------------
#define GEMM_IDS                                                                 \
    int tid = threadIdx.x, lane = tid & 31, wid = tid >> 5;                      \
    int wr = wid >> 1, wc = wid & 1;                                             \
    int srow = tid >> 1, shalf = tid & 1;                                        \
    int ar = wr * 32 + (lane & 15), ac = (lane >> 4) * 8;                        \
    int brw = wc * 32 + (lane & 7) + ((lane >> 4) * 8), bc = ((lane >> 3) & 1) * 8;

// ---------------- launch 1: LN + xz GEMM + conversions ----------------
__global__ void __launch_bounds__(128) gemm_xz(const float* __restrict__ x,
                                               const float* __restrict__ lnw,
                                               const float* __restrict__ lnb,
                                               const float* __restrict__ W_in,
                                               const float* __restrict__ conv_w,
                                               const float* __restrict__ adj,
                                               const float* __restrict__ W_out) {
    __shared__ __align__(16) __nv_bfloat16 Xs[64][264];
    __shared__ __align__(16) __nv_bfloat16 Ws[2][64][16];
    int m0 = blockIdx.y * 64, n0 = blockIdx.x * 64;
    GEMM_IDS
    (void)brw; (void)bc;

    {
        int r = tid >> 1, hf = tid & 1;
        const float4* xr = (const float4*)(x + (size_t)(m0 + r) * 256 + hf * 128);
        float s = 0.f, s2 = 0.f;
#pragma unroll 8
        for (int i = 0; i < 32; ++i) {
            float4 v = xr[i];
            s += v.x + v.y + v.z + v.w;
            s2 += v.x * v.x + v.y * v.y + v.z * v.z + v.w * v.w;
        }
        s  += __shfl_xor_sync(0xffffffffu, s, 1);
        s2 += __shfl_xor_sync(0xffffffffu, s2, 1);
        float mu = s * (1.f / 256.f);
        float var = s2 * (1.f / 256.f) - mu * mu;
        float rstd = rsqrtf(var + 1e-5f);
#pragma unroll 8
        for (int i = 0; i < 32; ++i) {
            float4 v = xr[i];
            int col = hf * 128 + i * 4;
            float4 w = *(const float4*)(lnw + col);
            float4 bb = *(const float4*)(lnb + col);
            Xs[r][col + 0] = __float2bfloat16((v.x - mu) * rstd * w.x + bb.x);
            Xs[r][col + 1] = __float2bfloat16((v.y - mu) * rstd * w.y + bb.y);
            Xs[r][col + 2] = __float2bfloat16((v.z - mu) * rstd * w.z + bb.z);
            Xs[r][col + 3] = __float2bfloat16((v.w - mu) * rstd * w.w + bb.w);
        }
    }

    float cfr[2][4][4] = {};
    auto ldW = [&](int k0) -> uint4 {
        const float* p = W_in + (size_t)(n0 + srow) * 256 + k0 + shalf * 8;
        return pack8(*(const float4*)p, *(const float4*)(p + 4));
    };
    uint4 pw = ldW(0);
    *(uint4*)&Ws[0][srow][shalf * 8] = pw;
    __syncthreads();
    int pb = 0;
    for (int k0 = 0; k0 < 256; k0 += 16, pb ^= 1) {
        if (k0 + 16 < 256) {
            pw = ldW(k0 + 16);
            *(uint4*)&Ws[pb ^ 1][srow][shalf * 8] = pw;
        }
        uint32_t afr[2][4], bfr[2][4];
        ldsm_x4(afr[0], smem_u32(&Xs[ar][k0 + ac]));
        ldsm_x4(afr[1], smem_u32(&Xs[ar + 16][k0 + ac]));
        {
            int brw2 = wc * 32 + (lane & 7) + ((lane >> 4) * 8), bc2 = ((lane >> 3) & 1) * 8;
            ldsm_x4(bfr[0], smem_u32(&Ws[pb][brw2][bc2]));
            ldsm_x4(bfr[1], smem_u32(&Ws[pb][brw2 + 16][bc2]));
        }
#pragma unroll
        for (int mt = 0; mt < 2; ++mt) {
            mma_bf16(cfr[mt][0], afr[mt], bfr[0] + 0);
            mma_bf16(cfr[mt][1], afr[mt], bfr[0] + 2);
            mma_bf16(cfr[mt][2], afr[mt], bfr[1] + 0);
            mma_bf16(cfr[mt][3], afr[mt], bfr[1] + 2);
        }
        __syncthreads();
    }
    int gr = lane >> 2, tc2 = (lane & 3) * 2;
#pragma unroll
    for (int mt = 0; mt < 2; ++mt)
#pragma unroll
        for (int nt = 0; nt < 4; ++nt)
#pragma unroll
            for (int e = 0; e < 4; ++e) {
                int m = m0 + wr * 32 + mt * 16 + gr + ((e >> 1) * 8);
                int n = n0 + wc * 32 + nt * 8 + tc2 + (e & 1);
                float v = cfr[mt][nt][e];
                if (n < 512) g_xpb[m * 512 + n] = __float2bfloat16(v);
                else         g_sz[m * 512 + (n - 512)] = v / (1.0f + __expf(-v));
            }

    int gtid = (blockIdx.y * gridDim.x + blockIdx.x) * 128 + tid;
    const int GT = 16 * 16 * 128;
    for (int i = gtid; i < 4 * 512 * 512; i += GT) {
        int kc = i >> 18, nn = (i >> 9) & 511, kk = i & 511;
        g_cwb[i] = __float2bfloat16(conv_w[nn * 2048 + kk * 4 + kc]);
    }
    for (int i = gtid; i < 2 * 512 * 512; i += GT)
        g_adjb[i] = __float2bfloat16(adj[i]);
    for (int i = gtid; i < 256 * 512; i += GT)
        g_Woutb[i] = __float2bfloat16(W_out[i]);
}

// ---------------- launch 2: conv GEMM (32-col stages, reg prefetch depth 2) ----------------
__global__ void __launch_bounds__(128) gemm_conv(const float* __restrict__ conv_b) {
    __shared__ __align__(16) __nv_bfloat16 As[2][64][32];
    __shared__ __align__(16) __nv_bfloat16 Ws[2][64][32];
    int m0 = blockIdx.y * 64, n0 = blockIdx.x * 64;
    GEMM_IDS
    float cfr[2][4][4] = {};
    auto ldA = [&](int it, uint4* v) {
        int kc = it >> 4, k0 = (it & 15) << 5;
        int tsrc = ((m0 + srow) & 511) - 3 + kc;
        v[0] = make_uint4(0u, 0u, 0u, 0u); v[1] = v[0];
        if (tsrc >= 0) {
            const __nv_bfloat16* p = &g_xpb[(long long)(m0 + srow - 3 + kc) * 512 + k0 + shalf * 8];
            v[0] = *(const uint4*)p;
            v[1] = *(const uint4*)(p + 16);
        }
    };
    auto ldW = [&](int it, uint4* v) {
        int kc = it >> 4, k0 = (it & 15) << 5;
        const __nv_bfloat16* p = &g_cwb[kc * 262144 + (n0 + srow) * 512 + k0 + shalf * 8];
        v[0] = *(const uint4*)p;
        v[1] = *(const uint4*)(p + 16);
    };
    uint4 ra[2], rw[2];
    ldA(0, ra); ldW(0, rw);
    *(uint4*)&As[0][srow][shalf * 8]      = ra[0];
    *(uint4*)&As[0][srow][16 + shalf * 8] = ra[1];
    *(uint4*)&Ws[0][srow][shalf * 8]      = rw[0];
    *(uint4*)&Ws[0][srow][16 + shalf * 8] = rw[1];
    ldA(1, ra); ldW(1, rw);
    for (int it = 0; it < 64; ++it) {
        __syncthreads();
        int pb = it & 1;
        if (it + 1 < 64) {
            int nb = pb ^ 1;
            *(uint4*)&As[nb][srow][shalf * 8]      = ra[0];
            *(uint4*)&As[nb][srow][16 + shalf * 8] = ra[1];
            *(uint4*)&Ws[nb][srow][shalf * 8]      = rw[0];
            *(uint4*)&Ws[nb][srow][16 + shalf * 8] = rw[1];
            if (it + 2 < 64) { ldA(it + 2, ra); ldW(it + 2, rw); }
        }
#pragma unroll
        for (int ks = 0; ks < 2; ++ks) {
            uint32_t afr[2][4], bfr[2][4];
            ldsm_x4(afr[0], smem_u32(&As[pb][ar][ks * 16 + ac]));
            ldsm_x4(afr[1], smem_u32(&As[pb][ar + 16][ks * 16 + ac]));
            ldsm_x4(bfr[0], smem_u32(&Ws[pb][brw][ks * 16 + bc]));
            ldsm_x4(bfr[1], smem_u32(&Ws[pb][brw + 16][ks * 16 + bc]));
#pragma unroll
            for (int mt = 0; mt < 2; ++mt) {
                mma_bf16(cfr[mt][0], afr[mt], bfr[0] + 0);
                mma_bf16(cfr[mt][1], afr[mt], bfr[0] + 2);
                mma_bf16(cfr[mt][2], afr[mt], bfr[1] + 0);
                mma_bf16(cfr[mt][3], afr[mt], bfr[1] + 2);
            }
        }
    }
    int gr = lane >> 2, tc2 = (lane & 3) * 2;
#pragma unroll
    for (int mt = 0; mt < 2; ++mt)
#pragma unroll
        for (int nt = 0; nt < 4; ++nt)
#pragma unroll
            for (int e = 0; e < 4; ++e) {
                int m = m0 + wr * 32 + mt * 16 + gr + ((e >> 1) * 8);
                int n = n0 + wc * 32 + nt * 8 + tc2 + (e & 1);
                float v = cfr[mt][nt][e] + conv_b[n];
                g_xact[m * 512 + n] = v / (1.0f + __expf(-v));
            }
}

// ---------------- launch 3: ssm + deg ----------------
__global__ void __launch_bounds__(128) ssm_deg(const float* __restrict__ W_xp,
                                               const float* __restrict__ W_dt,
                                               const float* __restrict__ b_dt,
                                               const float* __restrict__ adj) {
    __shared__ float xs[512];
    __shared__ float ssm_sh[33];
    __shared__ float rs[4];
    __shared__ int   ra[4];
    int row = blockIdx.x, tid = threadIdx.x, lane = tid & 31, wid = tid >> 5;
    int t = row & 511;

    for (int i = tid; i < 512; i += 128) xs[i] = g_xact[row * 512 + i];

    {
        const float* a = adj + (size_t)row * 512;
        float s = 0.f; int any = 0;
        for (int i = tid; i < t; i += 128) { float v = a[i]; s += v; any |= (v > 0.f); }
        for (int k = 16; k > 0; k >>= 1) {
            s += __shfl_xor_sync(0xffffffffu, s, k);
            any |= __shfl_xor_sync(0xffffffffu, any, k);
        }
        if (lane == 0) { rs[wid] = s; ra[wid] = any; }
    }
    __syncthreads();
    if (tid == 0) {
        float s = rs[0] + rs[1] + rs[2] + rs[3];
        int any = ra[0] | ra[1] | ra[2] | ra[3];
        g_invdeg[row] = 1.0f / fmaxf(s, 1.0f);
        g_any[row] = any ? 1.f : 0.f;
    }
    for (int o = wid; o < 33; o += 4) {
        float p = 0.f;
        for (int i = lane; i < 512; i += 32) p += xs[i] * W_xp[o * 512 + i];
        for (int k = 16; k > 0; k >>= 1) p += __shfl_xor_sync(0xffffffffu, p, k);
        if (lane == 0) ssm_sh[o] = p;
    }
    __syncthreads();
    if (tid < 16) {
        g_Bmb[row * 16 + tid] = __float2bfloat16(ssm_sh[1 + tid]);
        g_Cmb[row * 16 + tid] = __float2bfloat16(ssm_sh[17 + tid]);
    }
    float s0 = ssm_sh[0];
    for (int d = tid; d < 512; d += 128) {
        float v = s0 * W_dt[d] + b_dt[d];
        g_decay[row * 512 + d] = 1.0f / (1.0f + expf(v));  // exp(-softplus(v))
    }
}

// ---------------- launch 4: scan — dual-scatter serial, bubble-free chunks ----------------
__global__ void __launch_bounds__(128, 7) scan_kernel(const float* __restrict__ Wr,
                                                      const float* __restrict__ br) {
    __shared__ __align__(16) __nv_bfloat16 hist[512][16];       // 16384
    __shared__ __align__(16) unsigned char ubuf[3][2048];       // 6144 (tile / GP partial)
    __shared__ __align__(16) __nv_bfloat16 adjTf[32][32];       // 2048 in-chunk [j][t]
    __shared__ __align__(16) __nv_bfloat16 adjNx[32][32];       // 2048 next-chunk [j][t]
    __shared__ __align__(16) float xB_s[32][17];                // 2176 (padded)
    __shared__ __align__(16) float4 scal_s[32];                 // 512 (dec, cond, ivd[j+1])
    __shared__ __align__(16) __nv_bfloat16 gtmp[16];
    __shared__ float ivd0_s;

#define ADJS(w_) ((__nv_bfloat16(*)[32])ubuf[w_])
#define GPf(w_)  ((float(*)[16])ubuf[w_])

    int tid = threadIdx.x, lane = tid & 31, wid = tid >> 5;
    int seq = blockIdx.x, b = seq >> 9, d = seq & 511;
    const long long badj = (long long)b * 512 * 512;

    int n = lane & 15;
    bool hi = lane >= 16;
    int rbase = hi ? 16 : 0;

    __nv_bfloat162 Wr2[8], Greg2[8], Gnext2[8];
    float br_r = 0.f, hreg = 0.f;
    const __nv_bfloat162 zero2 = __floats2bfloat162_rn(0.f, 0.f);
    if (wid == 0) {
#pragma unroll
        for (int m = 0; m < 8; ++m)
            Wr2[m] = __floats2bfloat162_rn(Wr[n * 16 + 2 * m], Wr[n * 16 + 2 * m + 1]);
        br_r = br[n];
#pragma unroll
        for (int p = 0; p < 8; ++p) { Greg2[p] = zero2; Gnext2[p] = zero2; }
    }

    // ---- staging prefetch registers + lambdas ----
    uint4 preR[4];                 // warp1: adjNx rows; warp3: adjTf rows
    float pr_xa = 0.f, pr_dec = 0.f, pr_cond = 0.f, pr_ivdn = 0.f, pr_ivd0 = 0.f;
    uint4 prB0 = make_uint4(0,0,0,0), prB1 = make_uint4(0,0,0,0);

    auto prefT = [&](int cT) {  // adjTf source: adj[cT*32+lane][cT*32 ..]
        const __nv_bfloat16* src = &g_adjb[badj + (long long)(cT * 32 + lane) * 512 + cT * 32];
        preR[0] = *(const uint4*)(src + 0);  preR[1] = *(const uint4*)(src + 8);
        preR[2] = *(const uint4*)(src + 16); preR[3] = *(const uint4*)(src + 24);
    };
    auto prefN = [&](int cT) {  // adjNx source: adj[(cT+1)*32+lane][cT*32 ..]
        const __nv_bfloat16* src = &g_adjb[badj + (long long)((cT + 1) * 32 + lane) * 512 + cT * 32];
        preR[0] = *(const uint4*)(src + 0);  preR[1] = *(const uint4*)(src + 8);
        preR[2] = *(const uint4*)(src + 16); preR[3] = *(const uint4*)(src + 24);
    };
    auto prefS = [&](int cT) {  // warp2: scalars + B for chunk cT
        int row = b * 512 + cT * 32 + lane;
        pr_xa  = g_xact [(size_t)row * 512 + d];
        pr_dec = g_decay[(size_t)row * 512 + d];
        int t = cT * 32 + lane;
        pr_cond = (t > 0 && (g_any[t] > 0.f || g_any[512 + t] > 0.f)) ? 1.f : 0.f;
        pr_ivdn = (lane < 31) ? g_invdeg[row + 1] : 0.f;
        if (lane == 0) pr_ivd0 = g_invdeg[row];
        prB0 = *(const uint4*)&g_Bmb[row * 16];
        prB1 = *(const uint4*)&g_Bmb[row * 16 + 8];
    };

    if (wid == 1) prefN(0);
    else if (wid == 2) prefS(0);
    else if (wid == 3) prefT(0);

    for (int c = 0; c < 16; ++c) {
        int c0 = c << 5;

        // ================= PHASE A (STS only) =================
        if (wid == 0) {
            if (c > 0) {
#pragma unroll
                for (int p = 0; p < 8; ++p) {
                    int r0 = rbase + 2 * p, r1 = r0 + 1;
                    float lo = GPf(0)[r0][n] + GPf(1)[r0][n] + GPf(2)[r0][n];
                    float hv = GPf(0)[r1][n] + GPf(1)[r1][n] + GPf(2)[r1][n];
                    Greg2[p] = __hadd2(Gnext2[p], __floats2bfloat162_rn(lo, hv));
                    Gnext2[p] = zero2;
                }
            }
        } else if (wid == 1) {
            if (c < 15) {
                const __nv_bfloat16* rv = (const __nv_bfloat16*)preR;
#pragma unroll
                for (int s = 0; s < 32; ++s) adjNx[s][lane] = rv[s];
            }
        } else if (wid == 2) {
            scal_s[lane] = make_float4(pr_dec, pr_cond, pr_ivdn, 0.f);
            if (lane == 0) ivd0_s = pr_ivd0;
            const __nv_bfloat162* bp0 = (const __nv_bfloat162*)&prB0;
            const __nv_bfloat162* bp1 = (const __nv_bfloat162*)&prB1;
#pragma unroll
            for (int q = 0; q < 4; ++q) {
                float2 f0 = __bfloat1622float2(bp0[q]);
                xB_s[lane][2 * q]     = pr_xa * f0.x;
                xB_s[lane][2 * q + 1] = pr_xa * f0.y;
                float2 f1 = __bfloat1622float2(bp1[q]);
                xB_s[lane][8 + 2 * q]     = pr_xa * f1.x;
                xB_s[lane][8 + 2 * q + 1] = pr_xa * f1.y;
            }
        } else {
            const __nv_bfloat16* rv = (const __nv_bfloat16*)preR;
#pragma unroll
            for (int s = 0; s < 32; ++s) adjTf[s][lane] = rv[s];
        }
        __syncthreads();

        // ================= PHASE B =================
        if (wid == 0) {
            if (!hi) {
                float g0 = __bfloat162float(__low2bfloat16(Greg2[0]));
                gtmp[n] = __float2bfloat16(g0 * ivd0_s);
            }
            __syncwarp();
            const bool donext = (c < 15);
#pragma unroll
            for (int j = 0; j < 32; ++j) {
                uint4 ga = *(const uint4*)&gtmp[0];
                uint4 gb = *(const uint4*)&gtmp[8];
                const __nv_bfloat162* g2a = (const __nv_bfloat162*)&ga;
                const __nv_bfloat162* g2b = (const __nv_bfloat162*)&gb;
                uint4 av0 = *(const uint4*)&adjTf[j][rbase];
                uint4 av1 = *(const uint4*)&adjTf[j][rbase + 8];
                __nv_bfloat162 av2[8];
                {
                    const __nv_bfloat162* a0 = (const __nv_bfloat162*)&av0;
                    const __nv_bfloat162* a1 = (const __nv_bfloat162*)&av1;
#pragma unroll
                    for (int p = 0; p < 4; ++p) { av2[p] = a0[p]; av2[4 + p] = a1[p]; }
                }
                float4 sc = scal_s[j];
                float xb = xB_s[j][n];
                // matvec in bf16x2
                __nv_bfloat162 a0 = __hmul2(Wr2[0], g2a[0]);
                __nv_bfloat162 a1 = __hmul2(Wr2[1], g2a[1]);
                __nv_bfloat162 a2 = __hmul2(Wr2[2], g2a[2]);
                __nv_bfloat162 a3 = __hmul2(Wr2[3], g2a[3]);
                a0 = __hfma2(Wr2[4], g2b[0], a0);
                a1 = __hfma2(Wr2[5], g2b[1], a1);
                a2 = __hfma2(Wr2[6], g2b[2], a2);
                a3 = __hfma2(Wr2[7], g2b[3], a3);
                __nv_bfloat162 st = __hadd2(__hadd2(a0, a1), __hadd2(a2, a3));
                float2 sf = __bfloat1622float2(st);
                float accb = sf.x + sf.y + br_r;
                float bo = boost_silu(accb);
                float h = fmaf(hreg, sc.x, xb);
                h = fmaf(sc.y, bo, h);
                hreg = h;
                __nv_bfloat16 hb = __float2bfloat16(h);
                if (!hi) hist[c0 + j][n] = hb;
                __nv_bfloat162 h2 = __bfloat162bfloat162(hb);
                if (j + 1 < 32) {
                    const int jn = j + 1;
                    const int p = (jn & 15) >> 1;
                    Greg2[p] = __hfma2(av2[p], h2, Greg2[p]);
                    bool owner = ((jn >= 16) == hi);
                    if (owner) {
                        uint32_t bits = *(uint32_t*)&Greg2[p];
                        uint32_t sel = (jn & 1) ? (bits & 0xFFFF0000u) : (bits << 16);
                        float gv = __uint_as_float(sel) * sc.z;
                        gtmp[n] = __float2bfloat16(gv);
                    }
                    __syncwarp();
#pragma unroll
                    for (int p2 = 0; p2 < 8; ++p2)
                        if (p2 != p) Greg2[p2] = __hfma2(av2[p2], h2, Greg2[p2]);
                }
                if (donext) {
                    uint4 aw0 = *(const uint4*)&adjNx[j][rbase];
                    uint4 aw1 = *(const uint4*)&adjNx[j][rbase + 8];
                    const __nv_bfloat162* w0 = (const __nv_bfloat162*)&aw0;
                    const __nv_bfloat162* w1 = (const __nv_bfloat162*)&aw1;
#pragma unroll
                    for (int p2 = 0; p2 < 4; ++p2) {
                        Gnext2[p2]     = __hfma2(w0[p2], h2, Gnext2[p2]);
                        Gnext2[4 + p2] = __hfma2(w1[p2], h2, Gnext2[4 + p2]);
                    }
                }
            }
        } else {
            int w = wid - 1;
            float cfr[2][2][4] = {};
            if (c < 15 && w < c) {
                int r1 = (c + 1) << 5;
                auto ldTile = [&](int s_, uint4* v) {
#pragma unroll
                    for (int k = 0; k < 4; ++k) {
                        int e = lane + 32 * k, tt = e >> 2, q = e & 3;
                        v[k] = *(const uint4*)&g_adjb[badj + (long long)(r1 + tt) * 512 + s_ * 32 + q * 8];
                    }
                };
                uint4 pre[4];
                ldTile(w, pre);
                for (int st = w; st < c; st += 3) {
#pragma unroll
                    for (int k = 0; k < 4; ++k) {
                        int e = lane + 32 * k, tt = e >> 2, q = e & 3;
                        *(uint4*)&ADJS(w)[tt][q * 8] = pre[k];
                    }
                    __syncwarp();
                    if (st + 3 < c) ldTile(st + 3, pre);
                    int sb = st << 5;
                    uint32_t afr[4], bfr[4];
#pragma unroll
                    for (int kt = 0; kt < 2; ++kt) {
                        ldsm_x4t(bfr, smem_u32(&hist[sb + kt * 16 + (lane & 15)][(lane >> 4) * 8]));
#pragma unroll
                        for (int mt = 0; mt < 2; ++mt) {
                            ldsm_x4(afr, smem_u32(&ADJS(w)[mt * 16 + (lane & 15)][kt * 16 + (lane >> 4) * 8]));
                            mma_bf16(cfr[mt][0], afr, bfr + 0);
                            mma_bf16(cfr[mt][1], afr, bfr + 2);
                        }
                    }
                    __syncwarp();
                }
            }
            // per-warp extra jobs (prefetch for next chunk / P output)
            if (wid == 1) {
                if (c + 1 < 15) prefN(c + 1);
            } else if (wid == 2) {
                if (c < 15) prefS(c + 1);
            } else {  // wid == 3
                if (c < 15) prefT(c + 1);
                if (c > 0) {
                    int cp0 = (c - 1) << 5;
                    int rowg = b * 512 + cp0 + lane;
                    float y = dot16_bf16(&hist[cp0 + lane][0], &g_Cmb[rowg * 16]);
                    g_Pb[(long long)rowg * 512 + d] =
                        __float2bfloat16(y * g_sz[(long long)rowg * 512 + d]);
                }
            }
            // deposit GP partial (aliases tile buffer; all ldsm reads done)
            {
                int gr = lane >> 2, tc2 = (lane & 3) * 2;
#pragma unroll
                for (int mt = 0; mt < 2; ++mt)
#pragma unroll
                    for (int nt = 0; nt < 2; ++nt) {
                        *(float2*)&GPf(w)[mt * 16 + gr][nt * 8 + tc2] =
                            make_float2(cfr[mt][nt][0], cfr[mt][nt][1]);
                        *(float2*)&GPf(w)[mt * 16 + gr + 8][nt * 8 + tc2] =
                            make_float2(cfr[mt][nt][2], cfr[mt][nt][3]);
                    }
            }
        }
        __syncthreads();
    }

    if (tid < 32) {
        int cp0 = 15 << 5;
        int rowg = b * 512 + cp0 + tid;
        float y = dot16_bf16(&hist[cp0 + tid][0], &g_Cmb[rowg * 16]);
        g_Pb[(long long)rowg * 512 + d] =
            __float2bfloat16(y * g_sz[(long long)rowg * 512 + d]);
    }
#undef ADJS
#undef GPf
}

// ---------------- launch 5: out GEMM + residual ----------------
__global__ void __launch_bounds__(128) gemm_out(const float* __restrict__ x,
                                                float* __restrict__ out) {
    __shared__ __align__(16) __nv_bfloat16 As[2][64][16];
    __shared__ __align__(16) __nv_bfloat16 Ws[2][64][16];
    int m0 = blockIdx.y * 64, n0 = blockIdx.x * 64;
    GEMM_IDS
    float cfr[2][4][4] = {};
    *(uint4*)&As[0][srow][shalf * 8] = *(const uint4*)&g_Pb[(m0 + srow) * 512 + shalf * 8];
    *(uint4*)&Ws[0][srow][shalf * 8] = *(const uint4*)&g_Woutb[(n0 + srow) * 512 + shalf * 8];
    __syncthreads();
    int pb = 0;
    for (int k0 = 0; k0 < 512; k0 += 16, pb ^= 1) {
        if (k0 + 16 < 512) {
            *(uint4*)&As[pb ^ 1][srow][shalf * 8] =
                *(const uint4*)&g_Pb[(m0 + srow) * 512 + k0 + 16 + shalf * 8];
            *(uint4*)&Ws[pb ^ 1][srow][shalf * 8] =
                *(const uint4*)&g_Woutb[(n0 + srow) * 512 + k0 + 16 + shalf * 8];
        }
        uint32_t afr[2][4], bfr[2][4];
        ldsm_x4(afr[0], smem_u32(&As[pb][ar][ac]));
        ldsm_x4(afr[1], smem_u32(&As[pb][ar + 16][ac]));
        ldsm_x4(bfr[0], smem_u32(&Ws[pb][brw][bc]));
        ldsm_x4(bfr[1], smem_u32(&Ws[pb][brw + 16][bc]));
#pragma unroll
        for (int mt = 0; mt < 2; ++mt) {
            mma_bf16(cfr[mt][0], afr[mt], bfr[0] + 0);
            mma_bf16(cfr[mt][1], afr[mt], bfr[0] + 2);
            mma_bf16(cfr[mt][2], afr[mt], bfr[1] + 0);
            mma_bf16(cfr[mt][3], afr[mt], bfr[1] + 2);
        }
        __syncthreads();
    }
    int gr = lane >> 2, tc2 = (lane & 3) * 2;
#pragma unroll
    for (int mt = 0; mt < 2; ++mt)
#pragma unroll
        for (int nt = 0; nt < 4; ++nt)
#pragma unroll
            for (int e = 0; e < 4; ++e) {
                int m = m0 + wr * 32 + mt * 16 + gr + ((e >> 1) * 8);
                int n = n0 + wc * 32 + nt * 8 + tc2 + (e & 1);
                out[m * 256 + n] = cfr[mt][nt][e] + x[m * 256 + n];
            }
}

// ---------------- launch ----------------
extern "C" void kernel_launch(void* const* d_in, const int* in_sizes, int n_in,
                              void* d_out, int out_size) {
    const float* x      = (const float*)d_in[0];
    const float* adj    = (const float*)d_in[1];
    const float* ln_w   = (const float*)d_in[2];
    const float* ln_b   = (const float*)d_in[3];
    const float* W_in   = (const float*)d_in[4];
    const float* conv_w = (const float*)d_in[5];
    const float* conv_b = (const float*)d_in[6];
    const float* W_xp   = (const float*)d_in[7];
    const float* W_dt   = (const float*)d_in[8];
    const float* b_dt   = (const float*)d_in[9];
    const float* Wr     = (const float*)d_in[10];
    const float* br     = (const float*)d_in[11];
    const float* W_out  = (const float*)d_in[12];
    float* out = (float*)d_out;

    gemm_xz<<<dim3(16, 16), 128>>>(x, ln_w, ln_b, W_in, conv_w, adj, W_out);
    gemm_conv<<<dim3(8, 16), 128>>>(conv_b);
    ssm_deg<<<1024, 128>>>(W_xp, W_dt, b_dt, adj);
    scan_kernel<<<1024, 128>>>(Wr, br);
    gemm_out<<<dim3(4, 16), 128>>>(x, out);
}

// round 13
// speedup vs baseline: 1.1890x; 1.1890x over previous
#include <cuda_runtime.h>
#include <cuda_bf16.h>
#include <cstdint>

// B=2, S=512, D=256, N=16, DC=4, DI=512, CHUNK=32, rows=1024

// ---------------- scratch ----------------
__device__ __nv_bfloat16 g_xpb [1024*512];
__device__ float         g_sz  [1024*512];
__device__ float         g_xact[1024*512];
__device__ float         g_decay[1024*512];
__device__ __nv_bfloat16 g_Bmb [1024*16];
__device__ __nv_bfloat16 g_Cmb [1024*16];
__device__ float         g_invdeg[1024];
__device__ float         g_any [1024];
__device__ __nv_bfloat16 g_Pb  [1024*512];
__device__ __nv_bfloat16 g_Woutb[256*512];
__device__ __nv_bfloat16 g_adjb [2*512*512];
__device__ __nv_bfloat16 g_cwb  [4*512*512];   // [kc][n][k]

// ---------------- mma helpers ----------------
__device__ __forceinline__ uint32_t smem_u32(const void* p) {
    return (uint32_t)__cvta_generic_to_shared(p);
}
__device__ __forceinline__ void ldsm_x4(uint32_t* r, uint32_t a) {
    asm volatile("ldmatrix.sync.aligned.m8n8.x4.shared.b16 {%0,%1,%2,%3}, [%4];\n"
                 : "=r"(r[0]), "=r"(r[1]), "=r"(r[2]), "=r"(r[3]) : "r"(a));
}
__device__ __forceinline__ void ldsm_x4t(uint32_t* r, uint32_t a) {
    asm volatile("ldmatrix.sync.aligned.m8n8.x4.trans.shared.b16 {%0,%1,%2,%3}, [%4];\n"
                 : "=r"(r[0]), "=r"(r[1]), "=r"(r[2]), "=r"(r[3]) : "r"(a));
}
__device__ __forceinline__ void mma_bf16(float* c, const uint32_t* a, const uint32_t* b) {
    asm volatile(
        "mma.sync.aligned.m16n8k16.row.col.f32.bf16.bf16.f32 "
        "{%0,%1,%2,%3}, {%4,%5,%6,%7}, {%8,%9}, {%0,%1,%2,%3};\n"
        : "+f"(c[0]), "+f"(c[1]), "+f"(c[2]), "+f"(c[3])
        : "r"(a[0]), "r"(a[1]), "r"(a[2]), "r"(a[3]), "r"(b[0]), "r"(b[1]));
}
__device__ __forceinline__ uint4 pack8(float4 a, float4 b) {
    __nv_bfloat162 r0 = __floats2bfloat162_rn(a.x, a.y);
    __nv_bfloat162 r1 = __floats2bfloat162_rn(a.z, a.w);
    __nv_bfloat162 r2 = __floats2bfloat162_rn(b.x, b.y);
    __nv_bfloat162 r3 = __floats2bfloat162_rn(b.z, b.w);
    uint4 u;
    u.x = *(uint32_t*)&r0; u.y = *(uint32_t*)&r1;
    u.z = *(uint32_t*)&r2; u.w = *(uint32_t*)&r3;
    return u;
}
__device__ __forceinline__ float dot16_bf16(const __nv_bfloat16* h, const __nv_bfloat16* c) {
    uint4 h0 = *(const uint4*)h,       h1 = *(const uint4*)(h + 8);
    uint4 c0 = *(const uint4*)c,       c1 = *(const uint4*)(c + 8);
    const __nv_bfloat162* hp0 = (const __nv_bfloat162*)&h0;
    const __nv_bfloat162* hp1 = (const __nv_bfloat162*)&h1;
    const __nv_bfloat162* cp0 = (const __nv_bfloat162*)&c0;
    const __nv_bfloat162* cp1 = (const __nv_bfloat162*)&c1;
    float y = 0.f;
#pragma unroll
    for (int q = 0; q < 4; ++q) {
        float2 a = __bfloat1622float2(hp0[q]), bb = __bfloat1622float2(cp0[q]);
        y = fmaf(a.x, bb.x, y); y = fmaf(a.y, bb.y, y);
        float2 a1 = __bfloat1622float2(hp1[q]), b1 = __bfloat1622float2(cp1[q]);
        y = fmaf(a1.x, b1.x, y); y = fmaf(a1.y, b1.y, y);
    }
    return y;
}
// 0.1 * silu(x) via hardware tanh:  x*(0.05 + 0.05*tanh(0.5x))
__device__ __forceinline__ float boost_silu(float x) {
    float th;
    asm("tanh.approx.f32 %0, %1;" : "=f"(th) : "f"(x * 0.5f));
    return x * fmaf(th, 0.05f, 0.05f);
}

// ---------------- GEMM ids ----------------
#define GEMM_IDS                                                                 \
    int tid = threadIdx.x, lane = tid & 31, wid = tid >> 5;                      \
    int wr = wid >> 1, wc = wid & 1;                                             \
    int srow = tid >> 1, shalf = tid & 1;                                        \
    int ar = wr * 32 + (lane & 15), ac = (lane >> 4) * 8;                        \
    int brw = wc * 32 + (lane & 7) + ((lane >> 4) * 8), bc = ((lane >> 3) & 1) * 8;

// ---------------- launch 1: LN + xz GEMM + conversions ----------------
__global__ void __launch_bounds__(128) gemm_xz(const float* __restrict__ x,
                                               const float* __restrict__ lnw,
                                               const float* __restrict__ lnb,
                                               const float* __restrict__ W_in,
                                               const float* __restrict__ conv_w,
                                               const float* __restrict__ adj,
                                               const float* __restrict__ W_out) {
    __shared__ __align__(16) __nv_bfloat16 Xs[64][264];
    __shared__ __align__(16) __nv_bfloat16 Ws[2][64][16];
    int m0 = blockIdx.y * 64, n0 = blockIdx.x * 64;
    GEMM_IDS
    (void)brw; (void)bc;

    {
        int r = tid >> 1, hf = tid & 1;
        const float4* xr = (const float4*)(x + (size_t)(m0 + r) * 256 + hf * 128);
        float s = 0.f, s2 = 0.f;
#pragma unroll 8
        for (int i = 0; i < 32; ++i) {
            float4 v = xr[i];
            s += v.x + v.y + v.z + v.w;
            s2 += v.x * v.x + v.y * v.y + v.z * v.z + v.w * v.w;
        }
        s  += __shfl_xor_sync(0xffffffffu, s, 1);
        s2 += __shfl_xor_sync(0xffffffffu, s2, 1);
        float mu = s * (1.f / 256.f);
        float var = s2 * (1.f / 256.f) - mu * mu;
        float rstd = rsqrtf(var + 1e-5f);
#pragma unroll 8
        for (int i = 0; i < 32; ++i) {
            float4 v = xr[i];
            int col = hf * 128 + i * 4;
            float4 w = *(const float4*)(lnw + col);
            float4 bb = *(const float4*)(lnb + col);
            Xs[r][col + 0] = __float2bfloat16((v.x - mu) * rstd * w.x + bb.x);
            Xs[r][col + 1] = __float2bfloat16((v.y - mu) * rstd * w.y + bb.y);
            Xs[r][col + 2] = __float2bfloat16((v.z - mu) * rstd * w.z + bb.z);
            Xs[r][col + 3] = __float2bfloat16((v.w - mu) * rstd * w.w + bb.w);
        }
    }

    float cfr[2][4][4] = {};
    auto ldW = [&](int k0) -> uint4 {
        const float* p = W_in + (size_t)(n0 + srow) * 256 + k0 + shalf * 8;
        return pack8(*(const float4*)p, *(const float4*)(p + 4));
    };
    uint4 pw = ldW(0);
    *(uint4*)&Ws[0][srow][shalf * 8] = pw;
    __syncthreads();
    int pb = 0;
    for (int k0 = 0; k0 < 256; k0 += 16, pb ^= 1) {
        if (k0 + 16 < 256) {
            pw = ldW(k0 + 16);
            *(uint4*)&Ws[pb ^ 1][srow][shalf * 8] = pw;
        }
        uint32_t afr[2][4], bfr[2][4];
        ldsm_x4(afr[0], smem_u32(&Xs[ar][k0 + ac]));
        ldsm_x4(afr[1], smem_u32(&Xs[ar + 16][k0 + ac]));
        {
            int brw2 = wc * 32 + (lane & 7) + ((lane >> 4) * 8), bc2 = ((lane >> 3) & 1) * 8;
            ldsm_x4(bfr[0], smem_u32(&Ws[pb][brw2][bc2]));
            ldsm_x4(bfr[1], smem_u32(&Ws[pb][brw2 + 16][bc2]));
        }
#pragma unroll
        for (int mt = 0; mt < 2; ++mt) {
            mma_bf16(cfr[mt][0], afr[mt], bfr[0] + 0);
            mma_bf16(cfr[mt][1], afr[mt], bfr[0] + 2);
            mma_bf16(cfr[mt][2], afr[mt], bfr[1] + 0);
            mma_bf16(cfr[mt][3], afr[mt], bfr[1] + 2);
        }
        __syncthreads();
    }
    int gr = lane >> 2, tc2 = (lane & 3) * 2;
#pragma unroll
    for (int mt = 0; mt < 2; ++mt)
#pragma unroll
        for (int nt = 0; nt < 4; ++nt)
#pragma unroll
            for (int e = 0; e < 4; ++e) {
                int m = m0 + wr * 32 + mt * 16 + gr + ((e >> 1) * 8);
                int n = n0 + wc * 32 + nt * 8 + tc2 + (e & 1);
                float v = cfr[mt][nt][e];
                if (n < 512) g_xpb[m * 512 + n] = __float2bfloat16(v);
                else         g_sz[m * 512 + (n - 512)] = v / (1.0f + __expf(-v));
            }

    int gtid = (blockIdx.y * gridDim.x + blockIdx.x) * 128 + tid;
    const int GT = 16 * 16 * 128;
    for (int i = gtid; i < 4 * 512 * 512; i += GT) {
        int kc = i >> 18, nn = (i >> 9) & 511, kk = i & 511;
        g_cwb[i] = __float2bfloat16(conv_w[nn * 2048 + kk * 4 + kc]);
    }
    for (int i = gtid; i < 2 * 512 * 512; i += GT)
        g_adjb[i] = __float2bfloat16(adj[i]);
    for (int i = gtid; i < 256 * 512; i += GT)
        g_Woutb[i] = __float2bfloat16(W_out[i]);
}

// ---------------- launch 2: conv GEMM (32-col stages, reg prefetch depth 2) ----------------
__global__ void __launch_bounds__(128) gemm_conv(const float* __restrict__ conv_b) {
    __shared__ __align__(16) __nv_bfloat16 As[2][64][32];
    __shared__ __align__(16) __nv_bfloat16 Ws[2][64][32];
    int m0 = blockIdx.y * 64, n0 = blockIdx.x * 64;
    GEMM_IDS
    float cfr[2][4][4] = {};
    auto ldA = [&](int it, uint4* v) {
        int kc = it >> 4, k0 = (it & 15) << 5;
        int tsrc = ((m0 + srow) & 511) - 3 + kc;
        v[0] = make_uint4(0u, 0u, 0u, 0u); v[1] = v[0];
        if (tsrc >= 0) {
            const __nv_bfloat16* p = &g_xpb[(long long)(m0 + srow - 3 + kc) * 512 + k0 + shalf * 8];
            v[0] = *(const uint4*)p;
            v[1] = *(const uint4*)(p + 16);
        }
    };
    auto ldW = [&](int it, uint4* v) {
        int kc = it >> 4, k0 = (it & 15) << 5;
        const __nv_bfloat16* p = &g_cwb[kc * 262144 + (n0 + srow) * 512 + k0 + shalf * 8];
        v[0] = *(const uint4*)p;
        v[1] = *(const uint4*)(p + 16);
    };
    uint4 ra[2], rw[2];
    ldA(0, ra); ldW(0, rw);
    *(uint4*)&As[0][srow][shalf * 8]      = ra[0];
    *(uint4*)&As[0][srow][16 + shalf * 8] = ra[1];
    *(uint4*)&Ws[0][srow][shalf * 8]      = rw[0];
    *(uint4*)&Ws[0][srow][16 + shalf * 8] = rw[1];
    ldA(1, ra); ldW(1, rw);
    for (int it = 0; it < 64; ++it) {
        __syncthreads();
        int pb = it & 1;
        if (it + 1 < 64) {
            int nb = pb ^ 1;
            *(uint4*)&As[nb][srow][shalf * 8]      = ra[0];
            *(uint4*)&As[nb][srow][16 + shalf * 8] = ra[1];
            *(uint4*)&Ws[nb][srow][shalf * 8]      = rw[0];
            *(uint4*)&Ws[nb][srow][16 + shalf * 8] = rw[1];
            if (it + 2 < 64) { ldA(it + 2, ra); ldW(it + 2, rw); }
        }
#pragma unroll
        for (int ks = 0; ks < 2; ++ks) {
            uint32_t afr[2][4], bfr[2][4];
            ldsm_x4(afr[0], smem_u32(&As[pb][ar][ks * 16 + ac]));
            ldsm_x4(afr[1], smem_u32(&As[pb][ar + 16][ks * 16 + ac]));
            ldsm_x4(bfr[0], smem_u32(&Ws[pb][brw][ks * 16 + bc]));
            ldsm_x4(bfr[1], smem_u32(&Ws[pb][brw + 16][ks * 16 + bc]));
#pragma unroll
            for (int mt = 0; mt < 2; ++mt) {
                mma_bf16(cfr[mt][0], afr[mt], bfr[0] + 0);
                mma_bf16(cfr[mt][1], afr[mt], bfr[0] + 2);
                mma_bf16(cfr[mt][2], afr[mt], bfr[1] + 0);
                mma_bf16(cfr[mt][3], afr[mt], bfr[1] + 2);
            }
        }
    }
    int gr = lane >> 2, tc2 = (lane & 3) * 2;
#pragma unroll
    for (int mt = 0; mt < 2; ++mt)
#pragma unroll
        for (int nt = 0; nt < 4; ++nt)
#pragma unroll
            for (int e = 0; e < 4; ++e) {
                int m = m0 + wr * 32 + mt * 16 + gr + ((e >> 1) * 8);
                int n = n0 + wc * 32 + nt * 8 + tc2 + (e & 1);
                float v = cfr[mt][nt][e] + conv_b[n];
                g_xact[m * 512 + n] = v / (1.0f + __expf(-v));
            }
}

// ---------------- launch 3: ssm + deg ----------------
__global__ void __launch_bounds__(128) ssm_deg(const float* __restrict__ W_xp,
                                               const float* __restrict__ W_dt,
                                               const float* __restrict__ b_dt,
                                               const float* __restrict__ adj) {
    __shared__ float xs[512];
    __shared__ float ssm_sh[33];
    __shared__ float rs[4];
    __shared__ int   ra[4];
    int row = blockIdx.x, tid = threadIdx.x, lane = tid & 31, wid = tid >> 5;
    int t = row & 511;

    for (int i = tid; i < 512; i += 128) xs[i] = g_xact[row * 512 + i];

    {
        const float* a = adj + (size_t)row * 512;
        float s = 0.f; int any = 0;
        for (int i = tid; i < t; i += 128) { float v = a[i]; s += v; any |= (v > 0.f); }
        for (int k = 16; k > 0; k >>= 1) {
            s += __shfl_xor_sync(0xffffffffu, s, k);
            any |= __shfl_xor_sync(0xffffffffu, any, k);
        }
        if (lane == 0) { rs[wid] = s; ra[wid] = any; }
    }
    __syncthreads();
    if (tid == 0) {
        float s = rs[0] + rs[1] + rs[2] + rs[3];
        int any = ra[0] | ra[1] | ra[2] | ra[3];
        g_invdeg[row] = 1.0f / fmaxf(s, 1.0f);
        g_any[row] = any ? 1.f : 0.f;
    }
    for (int o = wid; o < 33; o += 4) {
        float p = 0.f;
        for (int i = lane; i < 512; i += 32) p += xs[i] * W_xp[o * 512 + i];
        for (int k = 16; k > 0; k >>= 1) p += __shfl_xor_sync(0xffffffffu, p, k);
        if (lane == 0) ssm_sh[o] = p;
    }
    __syncthreads();
    if (tid < 16) {
        g_Bmb[row * 16 + tid] = __float2bfloat16(ssm_sh[1 + tid]);
        g_Cmb[row * 16 + tid] = __float2bfloat16(ssm_sh[17 + tid]);
    }
    float s0 = ssm_sh[0];
    for (int d = tid; d < 512; d += 128) {
        float v = s0 * W_dt[d] + b_dt[d];
        g_decay[row * 512 + d] = 1.0f / (1.0f + expf(v));  // exp(-softplus(v))
    }
}

// ---------------- launch 4: scan (R10 + direct-gmem MMA A-fragments) ----------------
__global__ void __launch_bounds__(128, 7) scan_kernel(const float* __restrict__ Wr,
                                                      const float* __restrict__ br) {
    __shared__ __align__(16) __nv_bfloat16 hist[512][16];       // 16384
    __shared__ __align__(16) float GPbuf[3][32][16];            // 6144 gather partials
    __shared__ __align__(16) float Gsh[32][16];                 // 2048
    __shared__ __align__(16) __nv_bfloat16 adjTf[32][32];       // 2048, [j][t] = adj[c0+t][c0+j]
    __shared__ __align__(16) float xB_s[32][17];                // 2176 (padded)
    __shared__ __align__(16) float4 scal_s[32];                 // 512: (dec, cond, ivd[j+1], 0)
    __shared__ __align__(16) __nv_bfloat16 gtmp[16];
    __shared__ float ivd0_s;

    int tid = threadIdx.x, lane = tid & 31, wid = tid >> 5;
    int seq = blockIdx.x, b = seq >> 9, d = seq & 511;
    const long long badj = (long long)b * 512 * 512;

    int n = lane & 15;
    __nv_bfloat162 Wr2[8], Greg2[8];
    float br_r = 0.f, hreg = 0.f;
    if (wid == 0) {
#pragma unroll
        for (int m = 0; m < 8; ++m)
            Wr2[m] = __floats2bfloat162_rn(Wr[n * 16 + 2 * m], Wr[n * 16 + 2 * m + 1]);
        br_r = br[n];
    }

    // direct-gmem A-fragment loader: 16x16 bf16 tile at (row0, col0)
    int fr = lane >> 2, fc = (lane & 3) * 2;
    auto ldAfrag = [&](int row0, int col0, uint32_t* a) {
        const __nv_bfloat16* p = g_adjb + badj + (long long)(row0 + fr) * 512 + col0 + fc;
        a[0] = *(const uint32_t*)p;
        a[1] = *(const uint32_t*)(p + 8 * 512);
        a[2] = *(const uint32_t*)(p + 8);
        a[3] = *(const uint32_t*)(p + 8 * 512 + 8);
    };

    uint32_t finA[4][4];   // wid==1: finish-tile A frags [kt*2+mt][4]

    for (int c = 0; c < 16; ++c) {
        int c0 = c << 5;

        // ================= PHASE A =================
        if (wid == 1) {
            if (c == 0) {
                for (int e = lane; e < 512; e += 32) Gsh[e >> 4][e & 15] = 0.f;
            } else {
                // finish tile: adj[chunk c rows][chunk c-1 cols] (regs) x hist[c-1]
                float cfr2[2][2][4] = {};
                int sb = (c - 1) << 5;
                uint32_t bfr[4];
#pragma unroll
                for (int kt = 0; kt < 2; ++kt) {
                    ldsm_x4t(bfr, smem_u32(&hist[sb + kt * 16 + (lane & 15)][(lane >> 4) * 8]));
#pragma unroll
                    for (int mt = 0; mt < 2; ++mt) {
                        mma_bf16(cfr2[mt][0], finA[kt * 2 + mt], bfr + 0);
                        mma_bf16(cfr2[mt][1], finA[kt * 2 + mt], bfr + 2);
                    }
                }
                int gr = lane >> 2, tc2 = (lane & 3) * 2;
#pragma unroll
                for (int mt = 0; mt < 2; ++mt)
#pragma unroll
                    for (int nt = 0; nt < 2; ++nt)
#pragma unroll
                        for (int e = 0; e < 4; ++e) {
                            int r = mt * 16 + gr + (e >> 1) * 8;
                            int col = nt * 8 + tc2 + (e & 1);
                            Gsh[r][col] = GPbuf[0][r][col] + GPbuf[1][r][col] +
                                          GPbuf[2][r][col] + cfr2[mt][nt][e];
                        }
            }
        } else if (wid == 2) {
            int j = lane;
            int row = b * 512 + c0 + j;
            float xa = g_xact[(size_t)row * 512 + d];
            float dec = g_decay[(size_t)row * 512 + d];
            int t = c0 + j;
            float cond = (t > 0 && (g_any[t] > 0.f || g_any[512 + t] > 0.f)) ? 1.f : 0.f;
            float ivdn = (j < 31) ? g_invdeg[row + 1] : 0.f;
            scal_s[j] = make_float4(dec, cond, ivdn, 0.f);
            if (j == 0) ivd0_s = g_invdeg[row];
            uint4 bm = *(const uint4*)&g_Bmb[row * 16];
            __nv_bfloat162* bp = (__nv_bfloat162*)&bm;
#pragma unroll
            for (int q = 0; q < 8; ++q) {
                float2 f = __bfloat1622float2(bp[q]);
                xB_s[j][2 * q]     = xa * f.x;
                xB_s[j][2 * q + 1] = xa * f.y;
            }
        } else if (wid == 3) {
            __nv_bfloat16 rowv[32];
            const __nv_bfloat16* src = &g_adjb[badj + (long long)(c0 + lane) * 512 + c0];
            *(uint4*)&rowv[0]  = *(const uint4*)(src + 0);
            *(uint4*)&rowv[8]  = *(const uint4*)(src + 8);
            *(uint4*)&rowv[16] = *(const uint4*)(src + 16);
            *(uint4*)&rowv[24] = *(const uint4*)(src + 24);
#pragma unroll
            for (int s = 0; s < 32; ++s) adjTf[s][lane] = rowv[s];
        }
        __syncthreads();

        // ================= PHASE B =================
        if (wid == 0) {
            bool hi = lane >= 16;
            int rbase = hi ? 16 : 0;
#pragma unroll
            for (int p = 0; p < 8; ++p)
                Greg2[p] = __floats2bfloat162_rn(Gsh[rbase + 2 * p][n],
                                                 Gsh[rbase + 2 * p + 1][n]);
            if (!hi) gtmp[n] = __float2bfloat16(Gsh[0][n] * ivd0_s);
            __syncwarp();
#pragma unroll
            for (int j = 0; j < 32; ++j) {
                uint4 ga = *(const uint4*)&gtmp[0];
                uint4 gb = *(const uint4*)&gtmp[8];
                const __nv_bfloat162* g2a = (const __nv_bfloat162*)&ga;
                const __nv_bfloat162* g2b = (const __nv_bfloat162*)&gb;
                uint4 av0 = *(const uint4*)&adjTf[j][rbase];
                uint4 av1 = *(const uint4*)&adjTf[j][rbase + 8];
                __nv_bfloat162 av2[8];
                {
                    const __nv_bfloat162* a0 = (const __nv_bfloat162*)&av0;
                    const __nv_bfloat162* a1 = (const __nv_bfloat162*)&av1;
#pragma unroll
                    for (int p = 0; p < 4; ++p) { av2[p] = a0[p]; av2[4 + p] = a1[p]; }
                }
                float4 sc = scal_s[j];
                float xb = xB_s[j][n];
                __nv_bfloat162 a0 = __hmul2(Wr2[0], g2a[0]);
                __nv_bfloat162 a1 = __hmul2(Wr2[1], g2a[1]);
                __nv_bfloat162 a2 = __hmul2(Wr2[2], g2a[2]);
                __nv_bfloat162 a3 = __hmul2(Wr2[3], g2a[3]);
                a0 = __hfma2(Wr2[4], g2b[0], a0);
                a1 = __hfma2(Wr2[5], g2b[1], a1);
                a2 = __hfma2(Wr2[6], g2b[2], a2);
                a3 = __hfma2(Wr2[7], g2b[3], a3);
                __nv_bfloat162 st = __hadd2(__hadd2(a0, a1), __hadd2(a2, a3));
                float2 sf = __bfloat1622float2(st);
                float accb = sf.x + sf.y + br_r;
                float bo = boost_silu(accb);
                float h = fmaf(hreg, sc.x, xb);
                h = fmaf(sc.y, bo, h);
                hreg = h;
                __nv_bfloat16 hb = __float2bfloat16(h);
                if (!hi) hist[c0 + j][n] = hb;
                __nv_bfloat162 h2 = __bfloat162bfloat162(hb);
                if (j + 1 < 32) {
                    const int jn = j + 1;
                    const int p = (jn & 15) >> 1;
                    Greg2[p] = __hfma2(av2[p], h2, Greg2[p]);
                    bool owner = ((jn >= 16) == hi);
                    if (owner) {
                        uint32_t bits = *(uint32_t*)&Greg2[p];
                        uint32_t sel = (jn & 1) ? (bits & 0xFFFF0000u) : (bits << 16);
                        float gv = __uint_as_float(sel) * sc.z;
                        gtmp[n] = __float2bfloat16(gv);
                    }
                    __syncwarp();
#pragma unroll
                    for (int p2 = 0; p2 < 8; ++p2)
                        if (p2 != p) Greg2[p2] = __hfma2(av2[p2], h2, Greg2[p2]);
                }
            }
        } else {
            int w = wid - 1;
            float cfr[2][2][4] = {};
            if (c < 15 && w < c) {
                int r1 = (c + 1) << 5;
                for (int st = w; st < c; st += 3) {
                    // 16 LDG.32: A fragments straight from gmem
                    uint32_t afr4[4][4];
#pragma unroll
                    for (int kt = 0; kt < 2; ++kt)
#pragma unroll
                        for (int mt = 0; mt < 2; ++mt)
                            ldAfrag(r1 + mt * 16, st * 32 + kt * 16, afr4[kt * 2 + mt]);
                    int sb = st << 5;
                    uint32_t bfr[4];
#pragma unroll
                    for (int kt = 0; kt < 2; ++kt) {
                        ldsm_x4t(bfr, smem_u32(&hist[sb + kt * 16 + (lane & 15)][(lane >> 4) * 8]));
#pragma unroll
                        for (int mt = 0; mt < 2; ++mt) {
                            mma_bf16(cfr[mt][0], afr4[kt * 2 + mt], bfr + 0);
                            mma_bf16(cfr[mt][1], afr4[kt * 2 + mt], bfr + 2);
                        }
                    }
                }
            }
            // deposit GP partial
            {
                int gr = lane >> 2, tc2 = (lane & 3) * 2;
#pragma unroll
                for (int mt = 0; mt < 2; ++mt)
#pragma unroll
                    for (int nt = 0; nt < 2; ++nt) {
                        *(float2*)&GPbuf[w][mt * 16 + gr][nt * 8 + tc2] =
                            make_float2(cfr[mt][nt][0], cfr[mt][nt][1]);
                        *(float2*)&GPbuf[w][mt * 16 + gr + 8][nt * 8 + tc2] =
                            make_float2(cfr[mt][nt][2], cfr[mt][nt][3]);
                    }
            }
            if (wid == 1 && c < 15) {
                // prefetch finish-tile A frags for chunk c+1: rows (c+1)*32, cols c*32
                int r1 = (c + 1) << 5;
#pragma unroll
                for (int kt = 0; kt < 2; ++kt)
#pragma unroll
                    for (int mt = 0; mt < 2; ++mt)
                        ldAfrag(r1 + mt * 16, c0 + kt * 16, finA[kt * 2 + mt]);
            }
            if (wid == 3 && c > 0) {
                int cp0 = (c - 1) << 5;
                int rowg = b * 512 + cp0 + lane;
                float y = dot16_bf16(&hist[cp0 + lane][0], &g_Cmb[rowg * 16]);
                g_Pb[(long long)rowg * 512 + d] =
                    __float2bfloat16(y * g_sz[(long long)rowg * 512 + d]);
            }
        }
        __syncthreads();
    }

    if (tid < 32) {
        int cp0 = 15 << 5;
        int rowg = b * 512 + cp0 + tid;
        float y = dot16_bf16(&hist[cp0 + tid][0], &g_Cmb[rowg * 16]);
        g_Pb[(long long)rowg * 512 + d] =
            __float2bfloat16(y * g_sz[(long long)rowg * 512 + d]);
    }
}

// ---------------- launch 5: out GEMM + residual ----------------
__global__ void __launch_bounds__(128) gemm_out(const float* __restrict__ x,
                                                float* __restrict__ out) {
    __shared__ __align__(16) __nv_bfloat16 As[2][64][16];
    __shared__ __align__(16) __nv_bfloat16 Ws[2][64][16];
    int m0 = blockIdx.y * 64, n0 = blockIdx.x * 64;
    GEMM_IDS
    float cfr[2][4][4] = {};
    *(uint4*)&As[0][srow][shalf * 8] = *(const uint4*)&g_Pb[(m0 + srow) * 512 + shalf * 8];
    *(uint4*)&Ws[0][srow][shalf * 8] = *(const uint4*)&g_Woutb[(n0 + srow) * 512 + shalf * 8];
    __syncthreads();
    int pb = 0;
    for (int k0 = 0; k0 < 512; k0 += 16, pb ^= 1) {
        if (k0 + 16 < 512) {
            *(uint4*)&As[pb ^ 1][srow][shalf * 8] =
                *(const uint4*)&g_Pb[(m0 + srow) * 512 + k0 + 16 + shalf * 8];
            *(uint4*)&Ws[pb ^ 1][srow][shalf * 8] =
                *(const uint4*)&g_Woutb[(n0 + srow) * 512 + k0 + 16 + shalf * 8];
        }
        uint32_t afr[2][4], bfr[2][4];
        ldsm_x4(afr[0], smem_u32(&As[pb][ar][ac]));
        ldsm_x4(afr[1], smem_u32(&As[pb][ar + 16][ac]));
        ldsm_x4(bfr[0], smem_u32(&Ws[pb][brw][bc]));
        ldsm_x4(bfr[1], smem_u32(&Ws[pb][brw + 16][bc]));
#pragma unroll
        for (int mt = 0; mt < 2; ++mt) {
            mma_bf16(cfr[mt][0], afr[mt], bfr[0] + 0);
            mma_bf16(cfr[mt][1], afr[mt], bfr[0] + 2);
            mma_bf16(cfr[mt][2], afr[mt], bfr[1] + 0);
            mma_bf16(cfr[mt][3], afr[mt], bfr[1] + 2);
        }
        __syncthreads();
    }
    int gr = lane >> 2, tc2 = (lane & 3) * 2;
#pragma unroll
    for (int mt = 0; mt < 2; ++mt)
#pragma unroll
        for (int nt = 0; nt < 4; ++nt)
#pragma unroll
            for (int e = 0; e < 4; ++e) {
                int m = m0 + wr * 32 + mt * 16 + gr + ((e >> 1) * 8);
                int n = n0 + wc * 32 + nt * 8 + tc2 + (e & 1);
                out[m * 256 + n] = cfr[mt][nt][e] + x[m * 256 + n];
            }
}

// ---------------- launch ----------------
extern "C" void kernel_launch(void* const* d_in, const int* in_sizes, int n_in,
                              void* d_out, int out_size) {
    const float* x      = (const float*)d_in[0];
    const float* adj    = (const float*)d_in[1];
    const float* ln_w   = (const float*)d_in[2];
    const float* ln_b   = (const float*)d_in[3];
    const float* W_in   = (const float*)d_in[4];
    const float* conv_w = (const float*)d_in[5];
    const float* conv_b = (const float*)d_in[6];
    const float* W_xp   = (const float*)d_in[7];
    const float* W_dt   = (const float*)d_in[8];
    const float* b_dt   = (const float*)d_in[9];
    const float* Wr     = (const float*)d_in[10];
    const float* br     = (const float*)d_in[11];
    const float* W_out  = (const float*)d_in[12];
    float* out = (float*)d_out;

    gemm_xz<<<dim3(16, 16), 128>>>(x, ln_w, ln_b, W_in, conv_w, adj, W_out);
    gemm_conv<<<dim3(8, 16), 128>>>(conv_b);
    ssm_deg<<<1024, 128>>>(W_xp, W_dt, b_dt, adj);
    scan_kernel<<<1024, 128>>>(Wr, br);
    gemm_out<<<dim3(4, 16), 128>>>(x, out);
}